// round 12
// baseline (speedup 1.0000x reference)
#include <cuda_runtime.h>
#include <cstdint>

#define VOCAB 14
#define EMBED 10
#define HID   50
#define UW    25          // units per warp
#define KC    12          // k's cached in registers (48 regs)
#define SROWF 52          // sH row stride in floats
#define TLEN  2048
#define NBATCH 4096
#define ROWS  2           // batch rows per CTA (shared by both warps)

typedef unsigned long long ull;

// gW2[k*64 + w*32 + lane] = (0.5*Wi, 0.5*Wf, Wg, 0.5*Wo) for unit u = w*25+lane (lane<25; else 0)
// gX2[v*64 + w*32 + lane] = per-token gate init for unit u, same scaling
__device__ float4 gW2[HID * 64];
__device__ float4 gX2[VOCAB * 64];
__device__ float  gq[HID];
__device__ float  gc0;

// ---------------------------------------------------------------------------
__global__ void prep_kernel(const float* __restrict__ emb,
                            const float* __restrict__ W_ih,
                            const float* __restrict__ W_hh,
                            const float* __restrict__ b_ih,
                            const float* __restrict__ b_hh,
                            const float* __restrict__ W1,
                            const float* __restrict__ b1,
                            const float* __restrict__ W2,
                            const float* __restrict__ b2)
{
    int tid = threadIdx.x;

    for (int i = tid; i < HID * 64; i += blockDim.x) {
        int k = i / 64, s = i % 64;
        int w = s >> 5, L = s & 31;
        int u = w * UW + L;
        float4 v = make_float4(0.f, 0.f, 0.f, 0.f);
        if (L < UW && u < HID) {
            v.x = 0.5f * W_hh[(0 * HID + u) * HID + k];
            v.y = 0.5f * W_hh[(1 * HID + u) * HID + k];
            v.z =        W_hh[(2 * HID + u) * HID + k];
            v.w = 0.5f * W_hh[(3 * HID + u) * HID + k];
        }
        gW2[i] = v;
    }

    for (int i = tid; i < VOCAB * 64; i += blockDim.x) {
        int v = i / 64, s = i % 64;
        int w = s >> 5, L = s & 31;
        int u = w * UW + L;
        float4 x = make_float4(0.f, 0.f, 0.f, 0.f);
        if (L < UW && u < HID) {
            float* px = reinterpret_cast<float*>(&x);
            #pragma unroll
            for (int g = 0; g < 4; g++) {
                int c = g * HID + u;
                float s0 = b_ih[c] + b_hh[c];
                #pragma unroll
                for (int e = 0; e < EMBED; e++)
                    s0 += emb[v * EMBED + e] * W_ih[c * EMBED + e];
                px[g] = (g == 2) ? s0 : 0.5f * s0;
            }
        }
        gX2[i] = x;
    }

    for (int u = tid; u < HID; u += blockDim.x) {
        float s = 0.f;
        for (int m = 0; m < HID; m++) s += W2[m] * W1[m * HID + u];
        gq[u] = s;
    }
    if (tid == 0) {
        float s = b2[0];
        for (int m = 0; m < HID; m++) s += W2[m] * b1[m];
        gc0 = s;
    }
}

// ---------------------------------------------------------------------------
__device__ __forceinline__ ull ffma2(ull a, ull b, ull c) {
    ull d;
    asm("fma.rn.f32x2 %0, %1, %2, %3;" : "=l"(d) : "l"(a), "l"(b), "l"(c));
    return d;
}
__device__ __forceinline__ ull dup_(float x) {
    ull d;
    asm("mov.b64 %0, {%1, %1};" : "=l"(d) : "f"(x));
    return d;
}
__device__ __forceinline__ float lo_(ull v) { return __uint_as_float((unsigned)v); }
__device__ __forceinline__ float hi_(ull v) { return __uint_as_float((unsigned)(v >> 32)); }

__device__ __forceinline__ float tanhfast(float x) {
    float y;
    asm("tanh.approx.f32 %0, %1;" : "=f"(y) : "f"(x));
    return y;
}
// gate pre-scaled by 0.5: sigma(2y) = 0.5*tanh(y)+0.5
__device__ __forceinline__ float sigp(float y) { return fmaf(0.5f, tanhfast(y), 0.5f); }

// 4 k's of FFMA2 for all rows (weight ull pairs Wn = (if),(go); h-dups per row)
#define K4(W0a, W0b, W1a, W1b, W2a, W2b, W3a, W3b)                             \
    _Pragma("unroll")                                                          \
    for (int j = 0; j < ROWS; j++) {                                           \
        aif[j] = ffma2(W0a, hA[j], aif[j]);  ago[j] = ffma2(W0b, hA[j], ago[j]); \
        aif[j] = ffma2(W1a, hB[j], aif[j]);  ago[j] = ffma2(W1b, hB[j], ago[j]); \
        aif[j] = ffma2(W2a, hC[j], aif[j]);  ago[j] = ffma2(W2b, hC[j], ago[j]); \
        aif[j] = ffma2(W3a, hD[j], aif[j]);  ago[j] = ffma2(W3b, hD[j], ago[j]); \
    }

// ---------------------------------------------------------------------------
// CTA = 2 warps, 2 batch rows. UNIT-SPLIT: warp w computes gates for units
// [25w, 25w+25) over the FULL k-sum; each warp streams only its half of the
// weight table (1 LDG.128 per k). h shared via double-buffered SMEM, ONE
// __syncthreads per step. __launch_bounds__(64, 8) caps regs at 128 so
// 8 CTAs/SM stay resident -> 4 warps/SMSP of latency hiding.
// ---------------------------------------------------------------------------
__global__ __launch_bounds__(64, 8) void lstm_kernel(const int* __restrict__ tokens,
                                                     float* __restrict__ out)
{
    __shared__ __align__(16) float sH[2][ROWS][SROWF];

    const int lane = threadIdx.x & 31;
    const int wrp  = threadIdx.x >> 5;
    const int b0   = blockIdx.x * ROWS;
    const int base = wrp * 32 + lane;            // table slot
    const int u    = wrp * UW + lane;            // owned unit (live if lane<UW)
    const bool uok = (lane < UW);

    for (int i = threadIdx.x; i < 2 * ROWS * SROWF; i += 64)
        (&sH[0][0][0])[i] = 0.f;
    __syncthreads();

    float c[ROWS], h[ROWS];
    #pragma unroll
    for (int j = 0; j < ROWS; j++) { c[j] = 0.f; h[j] = 0.f; }

    // register-cached weights for k = 0..KC-1 (this warp's unit half)
    ull cw[KC * 2];
    #pragma unroll
    for (int k = 0; k < KC; k++) {
        ulonglong2 v = __ldg(reinterpret_cast<const ulonglong2*>(gW2 + k * 64 + base));
        cw[2 * k]     = v.x;    // (0.5Wi, 0.5Wf)
        cw[2 * k + 1] = v.y;    // (Wg, 0.5Wo)
    }

    const float4* __restrict__ Wp = gW2;
    const float4* __restrict__ Xp = gX2;

    const int* tp[ROWS];
    int tk[ROWS];
    #pragma unroll
    for (int j = 0; j < ROWS; j++) {
        tp[j] = tokens + (size_t)(b0 + j) * TLEN;
        tk[j] = __ldg(tp[j]);
    }

    for (int t = 0; t < TLEN; ++t) {
        const int p = t & 1;
        const int t2 = (t + 1 < TLEN) ? t + 1 : t;
        int tkn[ROWS];
        #pragma unroll
        for (int j = 0; j < ROWS; j++) tkn[j] = __ldg(tp[j] + t2);

        // accumulators: (i,f) and (g,o) packs, init from token gate-init table
        ull aif[ROWS], ago[ROWS];
        #pragma unroll
        for (int j = 0; j < ROWS; j++) {
            ulonglong2 v = __ldg(reinterpret_cast<const ulonglong2*>(Xp + tk[j] * 64 + base));
            aif[j] = v.x;  ago[j] = v.y;
        }

        // ---- cached k's (0..KC-1), groups of 4
        #pragma unroll
        for (int kg = 0; kg < KC; kg += 4) {
            ull hA[ROWS], hB[ROWS], hC[ROWS], hD[ROWS];
            #pragma unroll
            for (int j = 0; j < ROWS; j++) {
                float4 hv = *reinterpret_cast<const float4*>(&sH[p][j][kg]);
                hA[j] = dup_(hv.x);  hB[j] = dup_(hv.y);
                hC[j] = dup_(hv.z);  hD[j] = dup_(hv.w);
            }
            K4(cw[2*kg+0], cw[2*kg+1], cw[2*kg+2], cw[2*kg+3],
               cw[2*kg+4], cw[2*kg+5], cw[2*kg+6], cw[2*kg+7])
        }

        // ---- streamed k's (KC..47), groups of 4: one LDG.128 per k
        #pragma unroll
        for (int kg = KC; kg < 48; kg += 4) {
            ulonglong2 w0 = __ldg(reinterpret_cast<const ulonglong2*>(Wp + (kg + 0) * 64 + base));
            ulonglong2 w1 = __ldg(reinterpret_cast<const ulonglong2*>(Wp + (kg + 1) * 64 + base));
            ulonglong2 w2 = __ldg(reinterpret_cast<const ulonglong2*>(Wp + (kg + 2) * 64 + base));
            ulonglong2 w3 = __ldg(reinterpret_cast<const ulonglong2*>(Wp + (kg + 3) * 64 + base));
            ull hA[ROWS], hB[ROWS], hC[ROWS], hD[ROWS];
            #pragma unroll
            for (int j = 0; j < ROWS; j++) {
                float4 hv = *reinterpret_cast<const float4*>(&sH[p][j][kg]);
                hA[j] = dup_(hv.x);  hB[j] = dup_(hv.y);
                hC[j] = dup_(hv.z);  hD[j] = dup_(hv.w);
            }
            K4(w0.x, w0.y, w1.x, w1.y, w2.x, w2.y, w3.x, w3.y)
        }

        // ---- final pair k = 48, 49
        {
            ulonglong2 w0 = __ldg(reinterpret_cast<const ulonglong2*>(Wp + 48 * 64 + base));
            ulonglong2 w1 = __ldg(reinterpret_cast<const ulonglong2*>(Wp + 49 * 64 + base));
            #pragma unroll
            for (int j = 0; j < ROWS; j++) {
                float2 hv = *reinterpret_cast<const float2*>(&sH[p][j][48]);
                ull hA = dup_(hv.x), hB = dup_(hv.y);
                aif[j] = ffma2(w0.x, hA, aif[j]);  ago[j] = ffma2(w0.y, hA, ago[j]);
                aif[j] = ffma2(w1.x, hB, aif[j]);  ago[j] = ffma2(w1.y, hB, ago[j]);
            }
        }

        // ---- epilogue: one unit per lane; forward old h on pad tokens
        #pragma unroll
        for (int j = 0; j < ROWS; j++) {
            float i = sigp(lo_(aif[j]));
            float f = sigp(hi_(aif[j]));
            float g = tanhfast(lo_(ago[j]));
            float o = sigp(hi_(ago[j]));
            float cn = fmaf(f, c[j], i * g);
            float hn = o * tanhfast(cn);
            if (tk[j] != 0) { c[j] = cn; h[j] = hn; }
            if (uok) sH[1 - p][j][u] = h[j];     // unconditional state forward
        }
        __syncthreads();                          // one barrier per step

        #pragma unroll
        for (int j = 0; j < ROWS; j++) tk[j] = tkn[j];
    }

    // collapsed MLP head: out = sigmoid(c0 + q . h_final); final h in sH[0]
    if (wrp == 0 && lane < ROWS) {
        const int j = lane;
        float s = gc0;
        #pragma unroll 10
        for (int k = 0; k < HID; k++) s += gq[k] * sH[0][j][k];
        out[b0 + j] = 1.0f / (1.0f + __expf(-s));
    }
}

// ---------------------------------------------------------------------------
extern "C" void kernel_launch(void* const* d_in, const int* in_sizes, int n_in,
                              void* d_out, int out_size)
{
    const int*   tokens = (const int*)  d_in[0];
    const float* emb    = (const float*)d_in[1];
    const float* W_ih   = (const float*)d_in[2];
    const float* W_hh   = (const float*)d_in[3];
    const float* b_ih   = (const float*)d_in[4];
    const float* b_hh   = (const float*)d_in[5];
    const float* W1     = (const float*)d_in[6];
    const float* b1     = (const float*)d_in[7];
    const float* W2     = (const float*)d_in[8];
    const float* b2     = (const float*)d_in[9];
    float* out = (float*)d_out;

    prep_kernel<<<1, 256>>>(emb, W_ih, W_hh, b_ih, b_hh, W1, b1, W2, b2);
    lstm_kernel<<<NBATCH / ROWS, 64>>>(tokens, out);
}

// round 13
// speedup vs baseline: 1.3922x; 1.3922x over previous
#include <cuda_runtime.h>
#include <cstdint>

#define VOCAB 14
#define EMBED 10
#define HID   50
#define UW    25          // units per warp
#define KC    8           // k's cached in registers (32 regs)
#define SROWF 52          // sH row stride in floats
#define TLEN  2048
#define NBATCH 4096
#define ROWS  2           // batch rows per CTA (shared by both warps)

typedef unsigned long long ull;

// gW2[k*64 + w*32 + lane] = (0.5*Wi, 0.5*Wf, Wg, 0.5*Wo) for unit u = w*25+lane (lane<25; else 0)
// gX2[v*64 + w*32 + lane] = per-token gate init for unit u, same scaling
__device__ float4 gW2[HID * 64];
__device__ float4 gX2[VOCAB * 64];
__device__ float  gq[HID];
__device__ float  gc0;

// ---------------------------------------------------------------------------
__global__ void prep_kernel(const float* __restrict__ emb,
                            const float* __restrict__ W_ih,
                            const float* __restrict__ W_hh,
                            const float* __restrict__ b_ih,
                            const float* __restrict__ b_hh,
                            const float* __restrict__ W1,
                            const float* __restrict__ b1,
                            const float* __restrict__ W2,
                            const float* __restrict__ b2)
{
    int tid = threadIdx.x;

    for (int i = tid; i < HID * 64; i += blockDim.x) {
        int k = i / 64, s = i % 64;
        int w = s >> 5, L = s & 31;
        int u = w * UW + L;
        float4 v = make_float4(0.f, 0.f, 0.f, 0.f);
        if (L < UW && u < HID) {
            v.x = 0.5f * W_hh[(0 * HID + u) * HID + k];
            v.y = 0.5f * W_hh[(1 * HID + u) * HID + k];
            v.z =        W_hh[(2 * HID + u) * HID + k];
            v.w = 0.5f * W_hh[(3 * HID + u) * HID + k];
        }
        gW2[i] = v;
    }

    for (int i = tid; i < VOCAB * 64; i += blockDim.x) {
        int v = i / 64, s = i % 64;
        int w = s >> 5, L = s & 31;
        int u = w * UW + L;
        float4 x = make_float4(0.f, 0.f, 0.f, 0.f);
        if (L < UW && u < HID) {
            float* px = reinterpret_cast<float*>(&x);
            #pragma unroll
            for (int g = 0; g < 4; g++) {
                int c = g * HID + u;
                float s0 = b_ih[c] + b_hh[c];
                #pragma unroll
                for (int e = 0; e < EMBED; e++)
                    s0 += emb[v * EMBED + e] * W_ih[c * EMBED + e];
                px[g] = (g == 2) ? s0 : 0.5f * s0;
            }
        }
        gX2[i] = x;
    }

    for (int u = tid; u < HID; u += blockDim.x) {
        float s = 0.f;
        for (int m = 0; m < HID; m++) s += W2[m] * W1[m * HID + u];
        gq[u] = s;
    }
    if (tid == 0) {
        float s = b2[0];
        for (int m = 0; m < HID; m++) s += W2[m] * b1[m];
        gc0 = s;
    }
}

// ---------------------------------------------------------------------------
__device__ __forceinline__ ull ffma2(ull a, ull b, ull c) {
    ull d;
    asm("fma.rn.f32x2 %0, %1, %2, %3;" : "=l"(d) : "l"(a), "l"(b), "l"(c));
    return d;
}
__device__ __forceinline__ ull dup_(float x) {
    ull d;
    asm("mov.b64 %0, {%1, %1};" : "=l"(d) : "f"(x));
    return d;
}
__device__ __forceinline__ float lo_(ull v) { return __uint_as_float((unsigned)v); }
__device__ __forceinline__ float hi_(ull v) { return __uint_as_float((unsigned)(v >> 32)); }

__device__ __forceinline__ float tanhfast(float x) {
    float y;
    asm("tanh.approx.f32 %0, %1;" : "=f"(y) : "f"(x));
    return y;
}
// gate pre-scaled by 0.5: sigma(2y) = 0.5*tanh(y)+0.5
__device__ __forceinline__ float sigp(float y) { return fmaf(0.5f, tanhfast(y), 0.5f); }

// 4 k's of FFMA2 for all rows (weight ull pairs Wn = (if),(go); h-dups per row)
#define K4(W0a, W0b, W1a, W1b, W2a, W2b, W3a, W3b)                             \
    _Pragma("unroll")                                                          \
    for (int j = 0; j < ROWS; j++) {                                           \
        aif[j] = ffma2(W0a, hA[j], aif[j]);  ago[j] = ffma2(W0b, hA[j], ago[j]); \
        aif[j] = ffma2(W1a, hB[j], aif[j]);  ago[j] = ffma2(W1b, hB[j], ago[j]); \
        aif[j] = ffma2(W2a, hC[j], aif[j]);  ago[j] = ffma2(W2b, hC[j], ago[j]); \
        aif[j] = ffma2(W3a, hD[j], aif[j]);  ago[j] = ffma2(W3b, hD[j], ago[j]); \
    }

// ---------------------------------------------------------------------------
// CTA = 2 warps, 2 batch rows. UNIT-SPLIT: warp w computes gates for units
// [25w, 25w+25) over the FULL k-sum; each warp streams only its half of the
// weight table (1 LDG.128 per k). h shared via double-buffered SMEM, ONE
// __syncthreads per step. __launch_bounds__(64, 6) caps regs at ~170 — the
// measured spill-free point (R6) — giving 6 CTAs/SM = 3 warps/SMSP.
// ---------------------------------------------------------------------------
__global__ __launch_bounds__(64, 6) void lstm_kernel(const int* __restrict__ tokens,
                                                     float* __restrict__ out)
{
    __shared__ __align__(16) float sH[2][ROWS][SROWF];

    const int lane = threadIdx.x & 31;
    const int wrp  = threadIdx.x >> 5;
    const int b0   = blockIdx.x * ROWS;
    const int base = wrp * 32 + lane;            // table slot
    const int u    = wrp * UW + lane;            // owned unit (live if lane<UW)
    const bool uok = (lane < UW);

    for (int i = threadIdx.x; i < 2 * ROWS * SROWF; i += 64)
        (&sH[0][0][0])[i] = 0.f;
    __syncthreads();

    float c[ROWS], h[ROWS];
    #pragma unroll
    for (int j = 0; j < ROWS; j++) { c[j] = 0.f; h[j] = 0.f; }

    // register-cached weights for k = 0..KC-1 (this warp's unit half)
    ull cw[KC * 2];
    #pragma unroll
    for (int k = 0; k < KC; k++) {
        ulonglong2 v = __ldg(reinterpret_cast<const ulonglong2*>(gW2 + k * 64 + base));
        cw[2 * k]     = v.x;    // (0.5Wi, 0.5Wf)
        cw[2 * k + 1] = v.y;    // (Wg, 0.5Wo)
    }

    const float4* __restrict__ Wp = gW2;
    const float4* __restrict__ Xp = gX2;

    const int* tp[ROWS];
    int tk[ROWS];
    #pragma unroll
    for (int j = 0; j < ROWS; j++) {
        tp[j] = tokens + (size_t)(b0 + j) * TLEN;
        tk[j] = __ldg(tp[j]);
    }

    for (int t = 0; t < TLEN; ++t) {
        const int p = t & 1;
        const int t2 = (t + 1 < TLEN) ? t + 1 : t;
        int tkn[ROWS];
        #pragma unroll
        for (int j = 0; j < ROWS; j++) tkn[j] = __ldg(tp[j] + t2);

        // accumulators: (i,f) and (g,o) packs, init from token gate-init table
        ull aif[ROWS], ago[ROWS];
        #pragma unroll
        for (int j = 0; j < ROWS; j++) {
            ulonglong2 v = __ldg(reinterpret_cast<const ulonglong2*>(Xp + tk[j] * 64 + base));
            aif[j] = v.x;  ago[j] = v.y;
        }

        // ---- cached k's (0..KC-1), groups of 4
        #pragma unroll
        for (int kg = 0; kg < KC; kg += 4) {
            ull hA[ROWS], hB[ROWS], hC[ROWS], hD[ROWS];
            #pragma unroll
            for (int j = 0; j < ROWS; j++) {
                float4 hv = *reinterpret_cast<const float4*>(&sH[p][j][kg]);
                hA[j] = dup_(hv.x);  hB[j] = dup_(hv.y);
                hC[j] = dup_(hv.z);  hD[j] = dup_(hv.w);
            }
            K4(cw[2*kg+0], cw[2*kg+1], cw[2*kg+2], cw[2*kg+3],
               cw[2*kg+4], cw[2*kg+5], cw[2*kg+6], cw[2*kg+7])
        }

        // ---- streamed k's (KC..47), groups of 4: one LDG.128 per k
        #pragma unroll
        for (int kg = KC; kg < 48; kg += 4) {
            ulonglong2 w0 = __ldg(reinterpret_cast<const ulonglong2*>(Wp + (kg + 0) * 64 + base));
            ulonglong2 w1 = __ldg(reinterpret_cast<const ulonglong2*>(Wp + (kg + 1) * 64 + base));
            ulonglong2 w2 = __ldg(reinterpret_cast<const ulonglong2*>(Wp + (kg + 2) * 64 + base));
            ulonglong2 w3 = __ldg(reinterpret_cast<const ulonglong2*>(Wp + (kg + 3) * 64 + base));
            ull hA[ROWS], hB[ROWS], hC[ROWS], hD[ROWS];
            #pragma unroll
            for (int j = 0; j < ROWS; j++) {
                float4 hv = *reinterpret_cast<const float4*>(&sH[p][j][kg]);
                hA[j] = dup_(hv.x);  hB[j] = dup_(hv.y);
                hC[j] = dup_(hv.z);  hD[j] = dup_(hv.w);
            }
            K4(w0.x, w0.y, w1.x, w1.y, w2.x, w2.y, w3.x, w3.y)
        }

        // ---- final pair k = 48, 49
        {
            ulonglong2 w0 = __ldg(reinterpret_cast<const ulonglong2*>(Wp + 48 * 64 + base));
            ulonglong2 w1 = __ldg(reinterpret_cast<const ulonglong2*>(Wp + 49 * 64 + base));
            #pragma unroll
            for (int j = 0; j < ROWS; j++) {
                float2 hv = *reinterpret_cast<const float2*>(&sH[p][j][48]);
                ull hA = dup_(hv.x), hB = dup_(hv.y);
                aif[j] = ffma2(w0.x, hA, aif[j]);  ago[j] = ffma2(w0.y, hA, ago[j]);
                aif[j] = ffma2(w1.x, hB, aif[j]);  ago[j] = ffma2(w1.y, hB, ago[j]);
            }
        }

        // ---- epilogue: one unit per lane; forward old h on pad tokens
        #pragma unroll
        for (int j = 0; j < ROWS; j++) {
            float i = sigp(lo_(aif[j]));
            float f = sigp(hi_(aif[j]));
            float g = tanhfast(lo_(ago[j]));
            float o = sigp(hi_(ago[j]));
            float cn = fmaf(f, c[j], i * g);
            float hn = o * tanhfast(cn);
            if (tk[j] != 0) { c[j] = cn; h[j] = hn; }
            if (uok) sH[1 - p][j][u] = h[j];     // unconditional state forward
        }
        __syncthreads();                          // one barrier per step

        #pragma unroll
        for (int j = 0; j < ROWS; j++) tk[j] = tkn[j];
    }

    // collapsed MLP head: out = sigmoid(c0 + q . h_final); final h in sH[0]
    if (wrp == 0 && lane < ROWS) {
        const int j = lane;
        float s = gc0;
        #pragma unroll 10
        for (int k = 0; k < HID; k++) s += gq[k] * sH[0][j][k];
        out[b0 + j] = 1.0f / (1.0f + __expf(-s));
    }
}

// ---------------------------------------------------------------------------
extern "C" void kernel_launch(void* const* d_in, const int* in_sizes, int n_in,
                              void* d_out, int out_size)
{
    const int*   tokens = (const int*)  d_in[0];
    const float* emb    = (const float*)d_in[1];
    const float* W_ih   = (const float*)d_in[2];
    const float* W_hh   = (const float*)d_in[3];
    const float* b_ih   = (const float*)d_in[4];
    const float* b_hh   = (const float*)d_in[5];
    const float* W1     = (const float*)d_in[6];
    const float* b1     = (const float*)d_in[7];
    const float* W2     = (const float*)d_in[8];
    const float* b2     = (const float*)d_in[9];
    float* out = (float*)d_out;

    prep_kernel<<<1, 256>>>(emb, W_ih, W_hh, b_ih, b_hh, W1, b1, W2, b2);
    lstm_kernel<<<NBATCH / ROWS, 64>>>(tokens, out);
}

// round 14
// speedup vs baseline: 2.3789x; 1.7087x over previous
#include <cuda_runtime.h>
#include <cstdint>

#define VOCAB 14
#define EMBED 10
#define HID   50
#define KP    52          // padded k count (k=50,51 zero weights)
#define UW    25          // units per warp
#define SROWF 52          // sH row stride in floats
#define TLEN  2048
#define NBATCH 4096
#define ROWS  2           // batch rows per CTA (shared by both warps)

typedef unsigned long long ull;

// gW2[k*64 + w*32 + lane] = (0.5*Wi, 0.5*Wf, Wg, 0.5*Wo) for unit u = w*25+lane (lane<25; else 0)
//   k in [0,KP); rows k>=HID are all zero (loop padding).
// gX2[v*64 + w*32 + lane] = per-token gate init for unit u, same scaling
__device__ float4 gW2[KP * 64];
__device__ float4 gX2[VOCAB * 64];
__device__ float  gq[HID];
__device__ float  gc0;

// ---------------------------------------------------------------------------
__global__ void prep_kernel(const float* __restrict__ emb,
                            const float* __restrict__ W_ih,
                            const float* __restrict__ W_hh,
                            const float* __restrict__ b_ih,
                            const float* __restrict__ b_hh,
                            const float* __restrict__ W1,
                            const float* __restrict__ b1,
                            const float* __restrict__ W2,
                            const float* __restrict__ b2)
{
    int tid = threadIdx.x;

    for (int i = tid; i < KP * 64; i += blockDim.x) {
        int k = i / 64, s = i % 64;
        int w = s >> 5, L = s & 31;
        int u = w * UW + L;
        float4 v = make_float4(0.f, 0.f, 0.f, 0.f);
        if (k < HID && L < UW && u < HID) {
            v.x = 0.5f * W_hh[(0 * HID + u) * HID + k];
            v.y = 0.5f * W_hh[(1 * HID + u) * HID + k];
            v.z =        W_hh[(2 * HID + u) * HID + k];
            v.w = 0.5f * W_hh[(3 * HID + u) * HID + k];
        }
        gW2[i] = v;
    }

    for (int i = tid; i < VOCAB * 64; i += blockDim.x) {
        int v = i / 64, s = i % 64;
        int w = s >> 5, L = s & 31;
        int u = w * UW + L;
        float4 x = make_float4(0.f, 0.f, 0.f, 0.f);
        if (L < UW && u < HID) {
            float* px = reinterpret_cast<float*>(&x);
            #pragma unroll
            for (int g = 0; g < 4; g++) {
                int c = g * HID + u;
                float s0 = b_ih[c] + b_hh[c];
                #pragma unroll
                for (int e = 0; e < EMBED; e++)
                    s0 += emb[v * EMBED + e] * W_ih[c * EMBED + e];
                px[g] = (g == 2) ? s0 : 0.5f * s0;
            }
        }
        gX2[i] = x;
    }

    for (int u = tid; u < HID; u += blockDim.x) {
        float s = 0.f;
        for (int m = 0; m < HID; m++) s += W2[m] * W1[m * HID + u];
        gq[u] = s;
    }
    if (tid == 0) {
        float s = b2[0];
        for (int m = 0; m < HID; m++) s += W2[m] * b1[m];
        gc0 = s;
    }
}

// ---------------------------------------------------------------------------
__device__ __forceinline__ ull ffma2(ull a, ull b, ull c) {
    ull d;
    asm("fma.rn.f32x2 %0, %1, %2, %3;" : "=l"(d) : "l"(a), "l"(b), "l"(c));
    return d;
}
__device__ __forceinline__ ull dup_(float x) {
    ull d;
    asm("mov.b64 %0, {%1, %1};" : "=l"(d) : "f"(x));
    return d;
}
__device__ __forceinline__ float lo_(ull v) { return __uint_as_float((unsigned)v); }
__device__ __forceinline__ float hi_(ull v) { return __uint_as_float((unsigned)(v >> 32)); }

__device__ __forceinline__ float tanhfast(float x) {
    float y;
    asm("tanh.approx.f32 %0, %1;" : "=f"(y) : "f"(x));
    return y;
}
// gate pre-scaled by 0.5: sigma(2y) = 0.5*tanh(y)+0.5
__device__ __forceinline__ float sigp(float y) { return fmaf(0.5f, tanhfast(y), 0.5f); }

// ---------------------------------------------------------------------------
// CTA = 2 warps, 2 batch rows. UNIT-SPLIT: warp w computes gates for units
// [25w, 25w+25) over the FULL k-sum; each warp streams only its half of the
// weight table (1 LDG.128 per k). h shared via double-buffered SMEM, ONE
// __syncthreads per step. NO register weight cache and a runtime k-loop
// (unroll 1) keep the NATURAL register allocation low so more CTAs fit per
// SM — uncapped, so ptxas can never be forced into spilling.
// ---------------------------------------------------------------------------
__global__ __launch_bounds__(64) void lstm_kernel(const int* __restrict__ tokens,
                                                  float* __restrict__ out)
{
    __shared__ __align__(16) float sH[2][ROWS][SROWF];

    const int lane = threadIdx.x & 31;
    const int wrp  = threadIdx.x >> 5;
    const int b0   = blockIdx.x * ROWS;
    const int base = wrp * 32 + lane;            // table slot
    const int u    = wrp * UW + lane;            // owned unit (live if lane<UW)
    const bool uok = (lane < UW);

    for (int i = threadIdx.x; i < 2 * ROWS * SROWF; i += 64)
        (&sH[0][0][0])[i] = 0.f;
    __syncthreads();

    float c[ROWS], h[ROWS];
    #pragma unroll
    for (int j = 0; j < ROWS; j++) { c[j] = 0.f; h[j] = 0.f; }

    const float4* __restrict__ Wb = gW2 + base;  // this warp's weight column
    const float4* __restrict__ Xp = gX2;

    const int* tp[ROWS];
    int tk[ROWS];
    #pragma unroll
    for (int j = 0; j < ROWS; j++) {
        tp[j] = tokens + (size_t)(b0 + j) * TLEN;
        tk[j] = __ldg(tp[j]);
    }

    for (int t = 0; t < TLEN; ++t) {
        const int p = t & 1;
        const int t2 = (t + 1 < TLEN) ? t + 1 : t;
        int tkn[ROWS];
        #pragma unroll
        for (int j = 0; j < ROWS; j++) tkn[j] = __ldg(tp[j] + t2);

        // accumulators: (i,f) and (g,o) packs, init from token gate-init table
        ull aif[ROWS], ago[ROWS];
        #pragma unroll
        for (int j = 0; j < ROWS; j++) {
            ulonglong2 v = __ldg(reinterpret_cast<const ulonglong2*>(Xp + tk[j] * 64 + base));
            aif[j] = v.x;  ago[j] = v.y;
        }

        // ---- full k-sum, runtime loop, 4 k's per iteration
        const float4* wp = Wb;
        #pragma unroll 1
        for (int kg = 0; kg < KP; kg += 4) {
            ulonglong2 w0 = __ldg(reinterpret_cast<const ulonglong2*>(wp));
            ulonglong2 w1 = __ldg(reinterpret_cast<const ulonglong2*>(wp + 64));
            ulonglong2 w2 = __ldg(reinterpret_cast<const ulonglong2*>(wp + 128));
            ulonglong2 w3 = __ldg(reinterpret_cast<const ulonglong2*>(wp + 192));
            wp += 256;
            #pragma unroll
            for (int j = 0; j < ROWS; j++) {
                float4 hv = *reinterpret_cast<const float4*>(&sH[p][j][kg]);
                ull hA = dup_(hv.x), hB = dup_(hv.y);
                ull hC = dup_(hv.z), hD = dup_(hv.w);
                aif[j] = ffma2(w0.x, hA, aif[j]);  ago[j] = ffma2(w0.y, hA, ago[j]);
                aif[j] = ffma2(w1.x, hB, aif[j]);  ago[j] = ffma2(w1.y, hB, ago[j]);
                aif[j] = ffma2(w2.x, hC, aif[j]);  ago[j] = ffma2(w2.y, hC, ago[j]);
                aif[j] = ffma2(w3.x, hD, aif[j]);  ago[j] = ffma2(w3.y, hD, ago[j]);
            }
        }

        // ---- epilogue: one unit per lane; forward old h on pad tokens
        #pragma unroll
        for (int j = 0; j < ROWS; j++) {
            float i = sigp(lo_(aif[j]));
            float f = sigp(hi_(aif[j]));
            float g = tanhfast(lo_(ago[j]));
            float o = sigp(hi_(ago[j]));
            float cn = fmaf(f, c[j], i * g);
            float hn = o * tanhfast(cn);
            if (tk[j] != 0) { c[j] = cn; h[j] = hn; }
            if (uok) sH[1 - p][j][u] = h[j];     // unconditional state forward
        }
        __syncthreads();                          // one barrier per step

        #pragma unroll
        for (int j = 0; j < ROWS; j++) tk[j] = tkn[j];
    }

    // collapsed MLP head: out = sigmoid(c0 + q . h_final); final h in sH[0]
    if (wrp == 0 && lane < ROWS) {
        const int j = lane;
        float s = gc0;
        #pragma unroll 10
        for (int k = 0; k < HID; k++) s += gq[k] * sH[0][j][k];
        out[b0 + j] = 1.0f / (1.0f + __expf(-s));
    }
}

// ---------------------------------------------------------------------------
extern "C" void kernel_launch(void* const* d_in, const int* in_sizes, int n_in,
                              void* d_out, int out_size)
{
    const int*   tokens = (const int*)  d_in[0];
    const float* emb    = (const float*)d_in[1];
    const float* W_ih   = (const float*)d_in[2];
    const float* W_hh   = (const float*)d_in[3];
    const float* b_ih   = (const float*)d_in[4];
    const float* b_hh   = (const float*)d_in[5];
    const float* W1     = (const float*)d_in[6];
    const float* b1     = (const float*)d_in[7];
    const float* W2     = (const float*)d_in[8];
    const float* b2     = (const float*)d_in[9];
    float* out = (float*)d_out;

    prep_kernel<<<1, 256>>>(emb, W_ih, W_hh, b_ih, b_hh, W1, b1, W2, b2);
    lstm_kernel<<<NBATCH / ROWS, 64>>>(tokens, out);
}

// round 16
// speedup vs baseline: 13.1907x; 5.5449x over previous
#include <cuda_runtime.h>
#include <cuda_fp16.h>
#include <cstdint>

#define VOCAB 14
#define EMBED 10
#define HID   50
#define TLEN  2048
#define NBATCH 4096
#define NB    8              // batch rows per CTA
#define KD    64             // 50 h-units + 14 one-hot
#define HSTR  72             // hbuf k-stride (halves)
#define SSTR  68             // stage row stride (floats)

// A fragments, prepacked for mma.m16n8k16 row-major A:
// gAfrag[tile][lane][r], tile = (w*4+mt)*4+kt. fp16 W_aug rows r=4u+g
// (i,f,o rows pre-scaled 0.5 for sigmoid-via-tanh), cols k<50=W_hh, k>=50=XT.
__device__ uint32_t gAfrag[64][32][4];
__device__ float gq[HID];
__device__ float gc0;

// ---------------------------------------------------------------------------
__device__ __forceinline__ float waug_val(int row, int k,
                                          const float* emb, const float* W_ih,
                                          const float* W_hh, const float* b_ih,
                                          const float* b_hh)
{
    int u = row >> 2, g = row & 3;
    if (u >= HID) return 0.f;
    int c = g * HID + u;
    float v;
    if (k < HID) {
        v = W_hh[c * HID + k];
    } else {
        int vo = k - HID;
        v = b_ih[c] + b_hh[c];
        #pragma unroll
        for (int e = 0; e < EMBED; e++)
            v += emb[vo * EMBED + e] * W_ih[c * EMBED + e];
    }
    return (g == 2) ? v : 0.5f * v;   // pre-scale i,f,o for sigp
}

__global__ void prep_kernel(const float* __restrict__ emb,
                            const float* __restrict__ W_ih,
                            const float* __restrict__ W_hh,
                            const float* __restrict__ b_ih,
                            const float* __restrict__ b_hh,
                            const float* __restrict__ W1,
                            const float* __restrict__ b1,
                            const float* __restrict__ W2,
                            const float* __restrict__ b2)
{
    int tid = threadIdx.x;

    for (int idx = tid; idx < 64 * 32 * 4; idx += blockDim.x) {
        int r    = idx & 3;
        int lane = (idx >> 2) & 31;
        int tile = idx >> 7;
        int w  = tile >> 4, mt = (tile >> 2) & 3, kt = tile & 3;
        int gid = lane >> 2, t4 = lane & 3;
        int row_in = gid + ((r & 1) ? 8 : 0);      // r=1,3 -> +8 rows
        int col_in = 2 * t4 + ((r >= 2) ? 8 : 0);  // r=2,3 -> +8 cols
        int row = 64 * w + 16 * mt + row_in;
        int k   = 16 * kt + col_in;
        float v0 = waug_val(row, k,     emb, W_ih, W_hh, b_ih, b_hh);
        float v1 = waug_val(row, k + 1, emb, W_ih, W_hh, b_ih, b_hh);
        __half2 h2 = __floats2half2_rn(v0, v1);
        gAfrag[tile][lane][r] = *reinterpret_cast<uint32_t*>(&h2);
    }

    for (int u = tid; u < HID; u += blockDim.x) {
        float s = 0.f;
        for (int m = 0; m < HID; m++) s += W2[m] * W1[m * HID + u];
        gq[u] = s;
    }
    if (tid == 0) {
        float s = b2[0];
        for (int m = 0; m < HID; m++) s += W2[m] * b1[m];
        gc0 = s;
    }
}

// ---------------------------------------------------------------------------
__device__ __forceinline__ void mma16816(float d[4], const uint32_t a[4],
                                         const uint32_t b[2])
{
    asm("mma.sync.aligned.m16n8k16.row.col.f32.f16.f16.f32 "
        "{%0,%1,%2,%3}, {%4,%5,%6,%7}, {%8,%9}, {%0,%1,%2,%3};"
        : "+f"(d[0]), "+f"(d[1]), "+f"(d[2]), "+f"(d[3])
        : "r"(a[0]), "r"(a[1]), "r"(a[2]), "r"(a[3]), "r"(b[0]), "r"(b[1]));
}
__device__ __forceinline__ float tanhfast(float x) {
    float y; asm("tanh.approx.f32 %0, %1;" : "=f"(y) : "f"(x)); return y;
}
// gate pre-scaled by 0.5: sigma(2y) = 0.5*tanh(y)+0.5
__device__ __forceinline__ float sigp(float y) { return fmaf(0.5f, tanhfast(y), 0.5f); }

// ---------------------------------------------------------------------------
// CTA: 4 warps, 8 batches. gates[256x8] = A[256x64] @ h_aug[64x8] via 16
// HMMA m16n8k16 per warp per step (A stationary in registers). h_aug fp16
// double-buffered in SMEM (one __syncthreads/step); one-hot token columns
// fold the input GEMM + biases into the MMA. Warp w owns units 16w..16w+15.
// ---------------------------------------------------------------------------
__global__ __launch_bounds__(128) void lstm_kernel(const int* __restrict__ tokens,
                                                   float* __restrict__ out)
{
    __shared__ __align__(16) __half hbuf[2][NB][HSTR];   // h_aug[n][k], double-buffered
    __shared__ __align__(16) float  stage[4][NB][SSTR];  // per-warp D transpose stage
    __shared__ __align__(16) float  hfin[NB][52];
    __shared__ __align__(16) int    sTok[NB];

    const int tid  = threadIdx.x;
    const int wid  = tid >> 5, lane = tid & 31;
    const int gid  = lane >> 2, t4 = lane & 3;
    const int b0   = blockIdx.x * NB;

    for (int i = tid; i < 2 * NB * HSTR; i += 128)
        (&hbuf[0][0][0])[i] = __float2half(0.f);
    __syncthreads();

    int tcur = 0, pt0 = 0, pt1 = 0;
    if (wid == 0 && lane < NB) {
        tcur = __ldg(&tokens[(size_t)(b0 + lane) * TLEN]);
        sTok[lane] = tcur;
        hbuf[0][lane][HID + tcur] = __float2half(1.f);
        pt0 = tcur; pt1 = tcur;     // buf1 "prev" arbitrary: clearing a zero slot is harmless
    }

    // stationary A fragments (64 regs)
    uint32_t A[4][4][4];
    {
        const uint4* src = reinterpret_cast<const uint4*>(gAfrag);
        #pragma unroll
        for (int mt = 0; mt < 4; mt++)
            #pragma unroll
            for (int kt = 0; kt < 4; kt++) {
                uint4 v = __ldg(src + ((wid * 4 + mt) * 4 + kt) * 32 + lane);
                A[mt][kt][0] = v.x; A[mt][kt][1] = v.y;
                A[mt][kt][2] = v.z; A[mt][kt][3] = v.w;
            }
    }

    const int u_loc = lane >> 1, q = lane & 1;
    const int u_glob = wid * 16 + u_loc;
    const bool uok = (u_glob < HID);

    float h4[4], c4[4];
    #pragma unroll
    for (int i = 0; i < 4; i++) { h4[i] = 0.f; c4[i] = 0.f; }

    __syncthreads();

    for (int t = 0; t < TLEN; ++t) {
        const int p = t & 1;

        // B fragments: b0,b1 = h_aug[k=2t4(+16kt), k+1][n=gid]; b2,b3 = k+8
        uint32_t B[4][2];
        {
            const __half* hb = &hbuf[p][gid][0];
            #pragma unroll
            for (int kt = 0; kt < 4; kt++) {
                B[kt][0] = *reinterpret_cast<const uint32_t*>(hb + kt * 16 + 2 * t4);
                B[kt][1] = *reinterpret_cast<const uint32_t*>(hb + kt * 16 + 2 * t4 + 8);
            }
        }
        int4 tk4 = *reinterpret_cast<const int4*>(&sTok[4 * q]);
        int tnext = tcur;
        if (wid == 0 && lane < NB && t + 1 < TLEN)
            tnext = __ldg(&tokens[(size_t)(b0 + lane) * TLEN + t + 1]);

        // 16 HMMA: D[mt] = sum_kt A[mt][kt] @ B[kt]
        float d[4][4];
        #pragma unroll
        for (int mt = 0; mt < 4; mt++) {
            d[mt][0] = d[mt][1] = d[mt][2] = d[mt][3] = 0.f;
            #pragma unroll
            for (int kt = 0; kt < 4; kt++)
                mma16816(d[mt], A[mt][kt], B[kt]);
        }

        // transpose-stage D -> stage[wid][n][row_w]  (conflict-free STS.32)
        #pragma unroll
        for (int mt = 0; mt < 4; mt++) {
            int rw = mt * 16 + gid;
            stage[wid][2 * t4    ][rw]     = d[mt][0];
            stage[wid][2 * t4 + 1][rw]     = d[mt][1];
            stage[wid][2 * t4    ][rw + 8] = d[mt][2];
            stage[wid][2 * t4 + 1][rw + 8] = d[mt][3];
        }
        __syncwarp();

        // cells: lane owns unit u_glob, batches 4q..4q+3
        if (uok) {
            const int tks[4] = {tk4.x, tk4.y, tk4.z, tk4.w};
            #pragma unroll
            for (int bi = 0; bi < 4; bi++) {
                int n = 4 * q + bi;
                float4 gv = *reinterpret_cast<const float4*>(&stage[wid][n][4 * u_loc]);
                float i = sigp(gv.x);
                float f = sigp(gv.y);
                float g = tanhfast(gv.z);
                float o = sigp(gv.w);
                float cn = fmaf(f, c4[bi], i * g);
                float hn = o * tanhfast(cn);
                if (tks[bi] != 0) { c4[bi] = cn; h4[bi] = hn; }
                hbuf[1 - p][n][u_glob] = __float2half_rn(h4[bi]);  // unconditional forward
            }
        }

        // token / one-hot maintenance for next step (buf 1-p)
        if (wid == 0 && lane < NB) {
            if (p == 0) {
                hbuf[1][lane][HID + pt1] = __float2half(0.f);
                hbuf[1][lane][HID + tnext] = __float2half(1.f);
                pt1 = tnext;
            } else {
                hbuf[0][lane][HID + pt0] = __float2half(0.f);
                hbuf[0][lane][HID + tnext] = __float2half(1.f);
                pt0 = tnext;
            }
            sTok[lane] = tnext;
            tcur = tnext;
        }
        __syncthreads();
    }

    // head: out = sigmoid(c0 + q . h_final)  (h from fp32 registers)
    if (uok) {
        #pragma unroll
        for (int bi = 0; bi < 4; bi++)
            hfin[4 * q + bi][u_glob] = h4[bi];
    }
    __syncthreads();
    if (tid < NB) {
        float s = gc0;
        #pragma unroll 10
        for (int k = 0; k < HID; k++) s += gq[k] * hfin[tid][k];
        out[b0 + tid] = 1.0f / (1.0f + __expf(-s));
    }
}

// ---------------------------------------------------------------------------
extern "C" void kernel_launch(void* const* d_in, const int* in_sizes, int n_in,
                              void* d_out, int out_size)
{
    const int*   tokens = (const int*)  d_in[0];
    const float* emb    = (const float*)d_in[1];
    const float* W_ih   = (const float*)d_in[2];
    const float* W_hh   = (const float*)d_in[3];
    const float* b_ih   = (const float*)d_in[4];
    const float* b_hh   = (const float*)d_in[5];
    const float* W1     = (const float*)d_in[6];
    const float* b1     = (const float*)d_in[7];
    const float* W2     = (const float*)d_in[8];
    const float* b2     = (const float*)d_in[9];
    float* out = (float*)d_out;

    prep_kernel<<<1, 256>>>(emb, W_ih, W_hh, b_ih, b_hh, W1, b1, W2, b2);
    lstm_kernel<<<NBATCH / NB, 128>>>(tokens, out);
}